// round 17
// baseline (speedup 1.0000x reference)
#include <cuda_runtime.h>
#include <cuda_fp16.h>
#include <math.h>
#include <stdint.h>

// Problem constants
#define BATCH   2
#define NSEQ    2048
#define DMODEL  1024
#define NHEADS  16
#define DHEAD   64
#define MROWS   (BATCH * NSEQ)   // 4096

// ---------------------------------------------------------------------------
// Device scratch
// ---------------------------------------------------------------------------
__device__ float g_q[MROWS * DMODEL];                 // Q (fp32, LN'd in place)
__device__ __half g_kb[MROWS * DMODEL];               // K (fp16)
__device__ __half g_vb[MROWS * DMODEL];               // V (fp16)
__device__ __half g_xh[MROWS * DMODEL];               // x (fp16 plain)
__device__ __half g_wh[4 * DMODEL * DMODEL];          // W (fp16 plain)
__device__ __half g_af[MROWS * DMODEL];               // attn + q_norm (fp16)

// ---------------------------------------------------------------------------
// Helpers
// ---------------------------------------------------------------------------
__device__ __forceinline__ uint32_t smem_u32(const void* p) {
    uint32_t a;
    asm("{ .reg .u64 t; cvta.to.shared.u64 t, %1; cvt.u32.u64 %0, t; }" : "=r"(a) : "l"(p));
    return a;
}
__device__ __forceinline__ uint32_t packh2(float a, float b) {
    __half2 t = __floats2half2_rn(a, b);   // .x = a (low half)
    return *reinterpret_cast<uint32_t*>(&t);
}
// 2^x on packed fp16 pair via MUFU
__device__ __forceinline__ uint32_t ex2_h2(uint32_t u) {
    uint32_t r;
    asm("ex2.approx.f16x2 %0, %1;" : "=r"(r) : "r"(u));
    return r;
}
__device__ __forceinline__ void cpasync16(uint32_t dst, const void* src) {
    asm volatile("cp.async.cg.shared.global [%0], [%1], 16;" :: "r"(dst), "l"(src));
}
#define CP_COMMIT() asm volatile("cp.async.commit_group;" ::: "memory")
#define CP_WAIT(n)  asm volatile("cp.async.wait_group %0;" :: "n"(n) : "memory")

#define LDSM_X4(r, addr) \
    asm volatile("ldmatrix.sync.aligned.m8n8.x4.shared.b16 {%0,%1,%2,%3}, [%4];" \
        : "=r"((r)[0]), "=r"((r)[1]), "=r"((r)[2]), "=r"((r)[3]) : "r"(addr))
#define LDSM_X4_T(r, addr) \
    asm volatile("ldmatrix.sync.aligned.m8n8.x4.trans.shared.b16 {%0,%1,%2,%3}, [%4];" \
        : "=r"((r)[0]), "=r"((r)[1]), "=r"((r)[2]), "=r"((r)[3]) : "r"(addr))
#define MMAH(d, a, b) \
    asm volatile("mma.sync.aligned.m16n8k16.row.col.f32.f16.f16.f32 " \
        "{%0,%1,%2,%3}, {%4,%5,%6,%7}, {%8,%9}, {%0,%1,%2,%3};" \
        : "+f"((d)[0]), "+f"((d)[1]), "+f"((d)[2]), "+f"((d)[3]) \
        : "r"((a)[0]), "r"((a)[1]), "r"((a)[2]), "r"((a)[3]), "r"((b)[0]), "r"((b)[1]))

// ---------------------------------------------------------------------------
// Split kernel: x -> fp16; W0..W3 -> fp16 (plain). blockIdx.y: 0=x, 1..4=W
// ---------------------------------------------------------------------------
__global__ __launch_bounds__(256)
void split_all_kernel(const float* __restrict__ x,
                      const float* __restrict__ w0, const float* __restrict__ w1,
                      const float* __restrict__ w2, const float* __restrict__ w3,
                      __half* __restrict__ xh, __half* __restrict__ wh)
{
    const int y = blockIdx.y;
    int i = blockIdx.x * 256 + threadIdx.x;
    if (y == 0) {
        float4 v = ((const float4*)x)[i];
        ((__half2*)xh)[i * 2 + 0] = __floats2half2_rn(v.x, v.y);
        ((__half2*)xh)[i * 2 + 1] = __floats2half2_rn(v.z, v.w);
        return;
    }
    if (blockIdx.x >= DMODEL * DMODEL / 1024) return;
    const float* s = (y == 1) ? w0 : (y == 2) ? w1 : (y == 3) ? w2 : w3;
    size_t base2 = (size_t)(y - 1) * (DMODEL * DMODEL / 2);
    float4 v = ((const float4*)s)[i];
    ((__half2*)wh)[base2 + i * 2 + 0] = __floats2half2_rn(v.x, v.y);
    ((__half2*)wh)[base2 + i * 2 + 1] = __floats2half2_rn(v.z, v.w);
}

// ---------------------------------------------------------------------------
// GEMM body: C = A_fp16 @ W_fp16 + bias (fp32 accum).
// Tile 128x128, BK=32, 4-stage cp.async, 1 sync/iter, 2 CTAs/SM.
// outfmt: 0 = fp32 C, 1 = fp16 C.
// ---------------------------------------------------------------------------
#define A_STRIDE 80            // 32 fp16 = 64B, padded to 80B
#define B_STRIDE 272           // 128 fp16 = 256B, padded
#define ST_A 10240             // 128*80
#define ST_B 8704              // 32*272
#define NST 4
#define STAGE_SZ (ST_A + ST_B)          // 18944
#define GEMM_SMEM (NST * STAGE_SZ)      // 75776

__device__ __forceinline__
void gemm_body(const __half* __restrict__ A, const __half* __restrict__ B,
               const float* __restrict__ bias, void* __restrict__ Cout,
               int bm, int bn, int outfmt, char* smem)
{
    const uint32_t sb = smem_u32(smem);
    const int tid  = threadIdx.x;
    const int warp = tid >> 5;
    const int lane = tid & 31;

    const int arow = tid >> 1, ahalf = tid & 1;
    const __half* ag = A + (size_t)(bm + arow) * DMODEL + ahalf * 16;
    const uint32_t adst = (uint32_t)(arow * A_STRIDE + ahalf * 32);
    const int brow = tid >> 3, bc = tid & 7;
    const __half* bg = B + (size_t)brow * DMODEL + bn + bc * 16;
    const uint32_t bdst = (uint32_t)(brow * B_STRIDE + bc * 32);

    float acc[4][4][4];
#pragma unroll
    for (int mt = 0; mt < 4; mt++)
#pragma unroll
        for (int nt = 0; nt < 4; nt++)
#pragma unroll
            for (int e = 0; e < 4; e++) acc[mt][nt][e] = 0.0f;

    const int wm = (warp >> 2) * 64;
    const int wn = (warp & 3) * 32;
    const uint32_t lrow  = lane & 15;
    const uint32_t lhalf = lane >> 4;

#define ISSUE(t_) do { \
    uint32_t st_ = sb + ((t_) % NST) * STAGE_SZ; \
    int k0_ = (t_) * 32; \
    const __half* a_ = ag + k0_; \
    cpasync16(st_ + adst,      a_); \
    cpasync16(st_ + adst + 16, a_ + 8); \
    const __half* b_ = bg + (size_t)k0_ * DMODEL; \
    cpasync16(st_ + ST_A + bdst,      b_); \
    cpasync16(st_ + ST_A + bdst + 16, b_ + 8); \
} while (0)

#pragma unroll
    for (int t = 0; t < NST - 1; t++) { ISSUE(t); CP_COMMIT(); }

    for (int c = 0; c < 32; c++) {
        if (c < 32 - (NST - 1)) {
            CP_WAIT(NST - 2);
            __syncthreads();
            ISSUE(c + NST - 1);
            CP_COMMIT();
        } else {
            CP_WAIT(0);
            __syncthreads();
        }

        const uint32_t st = sb + (c % NST) * STAGE_SZ;
        const uint32_t aA = st + (wm + lrow) * A_STRIDE + lhalf * 16;
        const uint32_t aB = st + ST_A + lrow * B_STRIDE + (wn + 8 * lhalf) * 2;

#pragma unroll
        for (int ks = 0; ks < 2; ks++) {
            uint32_t ah[4][4];
#pragma unroll
            for (int mt = 0; mt < 4; mt++)
                LDSM_X4(ah[mt], aA + mt * (16 * A_STRIDE) + ks * 32);
            uint32_t bh[4][2];
#pragma unroll
            for (int nt2 = 0; nt2 < 2; nt2++) {
                uint32_t rh[4];
                LDSM_X4_T(rh, aB + ks * (16 * B_STRIDE) + nt2 * 32);
                bh[2 * nt2][0] = rh[0]; bh[2 * nt2][1] = rh[1];
                bh[2 * nt2 + 1][0] = rh[2]; bh[2 * nt2 + 1][1] = rh[3];
            }
#pragma unroll
            for (int mt = 0; mt < 4; mt++)
#pragma unroll
                for (int nt = 0; nt < 4; nt++)
                    MMAH(acc[mt][nt], ah[mt], bh[nt]);
        }
    }
#undef ISSUE

    __syncthreads();
    const int r0 = lane >> 2;
    const int c0 = (lane & 3) * 2;
#pragma unroll
    for (int mt = 0; mt < 4; mt++)
#pragma unroll
        for (int nt = 0; nt < 4; nt++) {
            int gr = bm + wm + mt * 16 + r0;
            int gc = bn + wn + nt * 8 + c0;
            float b0 = __ldg(bias + gc), b1 = __ldg(bias + gc + 1);
            float v00 = acc[mt][nt][0] + b0, v01 = acc[mt][nt][1] + b1;
            float v10 = acc[mt][nt][2] + b0, v11 = acc[mt][nt][3] + b1;
            if (outfmt == 0) {
                float* C = (float*)Cout;
                float2 a = {v00, v01}, b2 = {v10, v11};
                *(float2*)&C[(size_t)gr * DMODEL + gc] = a;
                *(float2*)&C[(size_t)(gr + 8) * DMODEL + gc] = b2;
            } else {
                __half* C = (__half*)Cout;
                *(__half2*)&C[(size_t)gr * DMODEL + gc] = __floats2half2_rn(v00, v01);
                *(__half2*)&C[(size_t)(gr + 8) * DMODEL + gc] = __floats2half2_rn(v10, v11);
            }
        }
}

// Fused QKV: grid.x = 24 (0..7 Q, 8..15 K, 16..23 V), grid.y = 32.
__global__ __launch_bounds__(256, 2)
void gemm_qkv(const __half* __restrict__ xh, const __half* __restrict__ wh,
              const float* __restrict__ bq, const float* __restrict__ bk,
              const float* __restrict__ bv,
              float* __restrict__ qout, __half* __restrict__ kout,
              __half* __restrict__ vout)
{
    extern __shared__ char smem[];
    const int which = blockIdx.x >> 3;           // 0=Q, 1=K, 2=V
    const int bn = (blockIdx.x & 7) * 128;
    const int bm = blockIdx.y * 128;
    const size_t WSZ = (size_t)DMODEL * DMODEL;
    const __half* B = wh + which * WSZ;
    const float* bias = (which == 0) ? bq : (which == 1) ? bk : bv;
    void* Cout = (which == 0) ? (void*)qout : (which == 1) ? (void*)kout : (void*)vout;
    gemm_body(xh, B, bias, Cout, bm, bn, (which == 0) ? 0 : 1, smem);
}

// O-projection: fp32 out.
__global__ __launch_bounds__(256, 2)
void gemm_o(const __half* __restrict__ A, const __half* __restrict__ B,
            const float* __restrict__ bias, float* __restrict__ C)
{
    extern __shared__ char smem[];
    gemm_body(A, B, bias, C, blockIdx.y * 128, blockIdx.x * 128, 0, smem);
}

// ---------------------------------------------------------------------------
// In-place LayerNorm over rows of length 1024. One block (256 thr) per row.
// ---------------------------------------------------------------------------
__global__ __launch_bounds__(256)
void ln_kernel(float* __restrict__ qio, const float* __restrict__ gamma,
               const float* __restrict__ beta)
{
    const int row = blockIdx.x;
    const int tid = threadIdx.x;
    float* rowp = qio + (size_t)row * DMODEL;

    float4 xv = *(const float4*)&rowp[tid * 4];
    float s  = xv.x + xv.y + xv.z + xv.w;
    float s2 = xv.x * xv.x + xv.y * xv.y + xv.z * xv.z + xv.w * xv.w;

#pragma unroll
    for (int o = 16; o > 0; o >>= 1) {
        s  += __shfl_xor_sync(0xffffffffu, s, o);
        s2 += __shfl_xor_sync(0xffffffffu, s2, o);
    }
    __shared__ float ws[8], ws2[8];
    if ((tid & 31) == 0) { ws[tid >> 5] = s; ws2[tid >> 5] = s2; }
    __syncthreads();
    float tot = 0.f, tot2 = 0.f;
#pragma unroll
    for (int i = 0; i < 8; i++) { tot += ws[i]; tot2 += ws2[i]; }

    const float inv = 1.0f / (float)DMODEL;
    float mu  = tot * inv;
    float var = tot2 * inv - mu * mu;
    float rs  = rsqrtf(var + 1e-5f);

    float4 gv = *(const float4*)&gamma[tid * 4];
    float4 bv = *(const float4*)&beta[tid * 4];
    float4 yv;
    yv.x = (xv.x - mu) * rs * gv.x + bv.x;
    yv.y = (xv.y - mu) * rs * gv.y + bv.y;
    yv.z = (xv.z - mu) * rs * gv.z + bv.z;
    yv.w = (xv.w - mu) * rs * gv.w + bv.w;
    *(float4*)&rowp[tid * 4] = yv;
}

// ---------------------------------------------------------------------------
// Flash attention, fp16 mma.sync. 4 warps x 32 q-rows (K/V fragments reused
// across 2 m-tiles -> LDSM traffic halved). 3-stage KV pipeline, 1 sync/iter.
// Softmax: Q pre-scaled by 0.125*log2(e); weights = ex2.approx.f16x2 (MUFU);
// denominator via extra MMA against an all-ones B fragment.
// ---------------------------------------------------------------------------
#define KVS 144
#define QS_BYTES (128 * KVS)
#define KV_BYTES (64 * KVS)
#define KV_NST 3
#define ATTN_SMEM (QS_BYTES + KV_NST * 2 * KV_BYTES)   // 73728

__global__ __launch_bounds__(128, 2)
void attn_f16(const float* __restrict__ q, const __half* __restrict__ kb,
              const __half* __restrict__ vb, __half* __restrict__ af)
{
    extern __shared__ char sm_[];
    const uint32_t sb = smem_u32(sm_);
    const int tid  = threadIdx.x;
    const int warp = tid >> 5;     // 0..3, each owns 32 q-rows
    const int lane = tid & 31;
    const int b = blockIdx.z, h = blockIdx.y;
    const int q0 = blockIdx.x * 128;

    const float* qg = q + ((size_t)(b * NSEQ + q0)) * DMODEL + h * DHEAD;
    const __half* kg = kb + ((size_t)(b * NSEQ)) * DMODEL + h * DHEAD;
    const __half* vg = vb + ((size_t)(b * NSEQ)) * DMODEL + h * DHEAD;

    // KV loader: 128 threads; row = tid>>1 (0..63), half-row (64B) = tid&1
    const int lr  = tid >> 1;
    const int lhb = (tid & 1) * 64;       // byte offset in smem row
    const int lhg = (tid & 1) * 32;       // half offset in global row
#define ISSUE_KV(t_) do { \
    uint32_t kd_ = sb + QS_BYTES + ((t_) % KV_NST) * (2 * KV_BYTES); \
    uint32_t vd_ = kd_ + KV_BYTES; \
    const __half* ks_ = kg + (size_t)((t_) * 64 + lr) * DMODEL + lhg; \
    const __half* vs_ = vg + (size_t)((t_) * 64 + lr) * DMODEL + lhg; \
    _Pragma("unroll") \
    for (int j = 0; j < 4; j++) { \
        cpasync16(kd_ + lr * KVS + lhb + j * 16, ks_ + j * 8); \
        cpasync16(vd_ + lr * KVS + lhb + j * 16, vs_ + j * 8); \
    } \
} while (0)

    ISSUE_KV(0); CP_COMMIT();
    ISSUE_KV(1); CP_COMMIT();

    // Q: fp32 -> fp16, scaled by d^-1/2 * log2(e) (scores in log2 domain)
    {
        const float qs = 0.125f * 1.44269504f;
        __half* Qs = (__half*)sm_;
#pragma unroll
        for (int i = 0; i < 16; i++) {
            int f = tid + i * 128;             // 0..2047 float4s
            int r = f >> 4, c4 = (f & 15) * 4;
            float4 v = *(const float4*)&qg[(size_t)r * DMODEL + c4];
            __half2 p0 = __floats2half2_rn(qs * v.x, qs * v.y);
            __half2 p1 = __floats2half2_rn(qs * v.z, qs * v.w);
            uint2 pk = { *reinterpret_cast<uint32_t*>(&p0), *reinterpret_cast<uint32_t*>(&p1) };
            *(uint2*)((char*)Qs + r * KVS + c4 * 2) = pk;
        }
    }
    __syncthreads();

    // Q a-fragments for both 16-row m-tiles of this warp
    uint32_t aQ[2][4][4];
#pragma unroll
    for (int mt = 0; mt < 2; mt++) {
        uint32_t qa = sb + (warp * 32 + mt * 16 + (lane & 15)) * KVS + (lane >> 4) * 16;
#pragma unroll
        for (int dc = 0; dc < 4; dc++) LDSM_X4(aQ[mt][dc], qa + dc * 32);
    }

    float oacc[2][8][4];
#pragma unroll
    for (int mt = 0; mt < 2; mt++)
#pragma unroll
        for (int j = 0; j < 8; j++)
#pragma unroll
            for (int e = 0; e < 4; e++) oacc[mt][j][e] = 0.0f;
    float dacc[2][4] = {{0.f,0.f,0.f,0.f},{0.f,0.f,0.f,0.f}};
    const uint32_t bone[2] = { 0x3C003C00u, 0x3C003C00u };   // fp16 1.0 x4

    const uint32_t lsel = (lane & 15), lhf = (lane >> 4);
    const int NT = NSEQ / 64;   // 32

    for (int t = 0; t < NT; t++) {
        if (t < NT - 2) {
            CP_WAIT(1);
            __syncthreads();
            ISSUE_KV(t + 2);
            CP_COMMIT();
        } else {
            CP_WAIT(0);
            __syncthreads();
        }

        const uint32_t ks = sb + QS_BYTES + (t % KV_NST) * (2 * KV_BYTES);
        const uint32_t vs = ks + KV_BYTES;

        // S (log2 domain) = Qs @ K^T for both m-tiles; K fragments loaded once
        float sacc[2][8][4];
#pragma unroll
        for (int mt = 0; mt < 2; mt++)
#pragma unroll
            for (int j = 0; j < 8; j++)
#pragma unroll
                for (int e = 0; e < 4; e++) sacc[mt][j][e] = 0.0f;

        const uint32_t kaddr = ks + lsel * KVS + lhf * 16;
#pragma unroll
        for (int dc = 0; dc < 4; dc++)
#pragma unroll
            for (int np = 0; np < 4; np++) {
                uint32_t r[4];
                LDSM_X4(r, kaddr + np * (16 * KVS) + dc * 32);
                uint32_t b0[2] = { r[0], r[2] };
                uint32_t b1[2] = { r[1], r[3] };
                MMAH(sacc[0][2 * np],     aQ[0][dc], b0);
                MMAH(sacc[0][2 * np + 1], aQ[0][dc], b1);
                MMAH(sacc[1][2 * np],     aQ[1][dc], b0);
                MMAH(sacc[1][2 * np + 1], aQ[1][dc], b1);
            }

        // P = 2^S via MUFU on fp16 pairs
        uint32_t plo[2][8], phi[2][8];
#pragma unroll
        for (int mt = 0; mt < 2; mt++)
#pragma unroll
            for (int nt = 0; nt < 8; nt++) {
                plo[mt][nt] = ex2_h2(packh2(sacc[mt][nt][0], sacc[mt][nt][1]));
                phi[mt][nt] = ex2_h2(packh2(sacc[mt][nt][2], sacc[mt][nt][3]));
            }

        // O += P @ V ; den += P @ ones ; V fragments loaded once per warp
        const uint32_t vaddr = vs + lsel * KVS + lhf * 16;
#pragma unroll
        for (int kc = 0; kc < 4; kc++) {
            uint32_t aP0[4] = { plo[0][2*kc], phi[0][2*kc], plo[0][2*kc+1], phi[0][2*kc+1] };
            uint32_t aP1[4] = { plo[1][2*kc], phi[1][2*kc], plo[1][2*kc+1], phi[1][2*kc+1] };
            MMAH(dacc[0], aP0, bone);
            MMAH(dacc[1], aP1, bone);
#pragma unroll
            for (int dg = 0; dg < 4; dg++) {
                uint32_t r[4];
                LDSM_X4_T(r, vaddr + kc * (16 * KVS) + dg * 32);
                uint32_t b0[2] = { r[0], r[1] };
                uint32_t b1[2] = { r[2], r[3] };
                MMAH(oacc[0][2 * dg],     aP0, b0);
                MMAH(oacc[0][2 * dg + 1], aP0, b1);
                MMAH(oacc[1][2 * dg],     aP1, b0);
                MMAH(oacc[1][2 * dg + 1], aP1, b1);
            }
        }
    }
#undef ISSUE_KV

    // Epilogue per m-tile: out = O/den + q_norm -> fp16
    const int r0 = lane >> 2;
    const int c0 = (lane & 3) * 2;
#pragma unroll
    for (int mt = 0; mt < 2; mt++) {
        const float inv0 = 1.0f / (1e-8f + dacc[mt][0]);
        const float inv8 = 1.0f / (1e-8f + dacc[mt][2]);
        const int row0 = q0 + warp * 32 + mt * 16 + r0;
        const float* q0p = q + ((size_t)(b * NSEQ + row0)) * DMODEL + h * DHEAD;
        const float* q8p = q0p + 8 * DMODEL;
        const size_t ob0 = (size_t)(b * NSEQ + row0) * DMODEL + h * DHEAD;
        const size_t ob8 = ob0 + 8 * DMODEL;
#pragma unroll
        for (int nt = 0; nt < 8; nt++) {
            int col = nt * 8 + c0;
            float2 qv0 = *(const float2*)&q0p[col];
            float2 qv8 = *(const float2*)&q8p[col];
            float o00 = oacc[mt][nt][0] * inv0 + qv0.x;
            float o01 = oacc[mt][nt][1] * inv0 + qv0.y;
            float o80 = oacc[mt][nt][2] * inv8 + qv8.x;
            float o81 = oacc[mt][nt][3] * inv8 + qv8.y;
            *(__half2*)&af[ob0 + col] = __floats2half2_rn(o00, o01);
            *(__half2*)&af[ob8 + col] = __floats2half2_rn(o80, o81);
        }
    }
}

// ---------------------------------------------------------------------------
// Launch
// ---------------------------------------------------------------------------
extern "C" void kernel_launch(void* const* d_in, const int* in_sizes, int n_in,
                              void* d_out, int out_size)
{
    (void)in_sizes; (void)n_in; (void)out_size;
    const float* x    = (const float*)d_in[0];
    const float* Wq   = (const float*)d_in[1];
    const float* bq   = (const float*)d_in[2];
    const float* Wk   = (const float*)d_in[3];
    const float* bk   = (const float*)d_in[4];
    const float* Wv   = (const float*)d_in[5];
    const float* bv   = (const float*)d_in[6];
    const float* Wo   = (const float*)d_in[7];
    const float* bo   = (const float*)d_in[8];
    const float* ln_g = (const float*)d_in[9];
    const float* ln_b = (const float*)d_in[10];
    float* out = (float*)d_out;

    float* qp;
    __half *kbp, *vbp, *xh, *wh, *af;
    cudaGetSymbolAddress((void**)&qp, g_q);
    cudaGetSymbolAddress((void**)&kbp, g_kb);
    cudaGetSymbolAddress((void**)&vbp, g_vb);
    cudaGetSymbolAddress((void**)&xh, g_xh);
    cudaGetSymbolAddress((void**)&wh, g_wh);
    cudaGetSymbolAddress((void**)&af, g_af);

    cudaFuncSetAttribute(gemm_qkv, cudaFuncAttributeMaxDynamicSharedMemorySize, GEMM_SMEM);
    cudaFuncSetAttribute(gemm_o,   cudaFuncAttributeMaxDynamicSharedMemorySize, GEMM_SMEM);
    cudaFuncSetAttribute(attn_f16, cudaFuncAttributeMaxDynamicSharedMemorySize, ATTN_SMEM);

    const size_t WSZ = (size_t)DMODEL * DMODEL;

    // 0: convert x + all 4 weights to fp16
    split_all_kernel<<<dim3(MROWS * DMODEL / 1024, 5), 256>>>(x, Wq, Wk, Wv, Wo, xh, wh);
    // 1: fused QKV projection (Q -> fp32 for LN, K/V -> fp16 direct)
    gemm_qkv<<<dim3(24, MROWS / 128), 256, GEMM_SMEM>>>(xh, wh, bq, bk, bv, qp, kbp, vbp);
    // 2: LN(q) in place
    ln_kernel<<<MROWS, 256>>>(qp, ln_g, ln_b);
    // 3: attention (profiled slot) -> (attn + q_norm) fp16
    attn_f16<<<dim3(NSEQ / 128, NHEADS, BATCH), 128, ATTN_SMEM>>>(qp, kbp, vbp, af);
    // 4: out = (attn + q_norm) @ Wo + bo
    gemm_o<<<dim3(DMODEL / 128, MROWS / 128), 256, GEMM_SMEM>>>(af, wh + 3 * WSZ, bo, out);
}